// round 15
// baseline (speedup 1.0000x reference)
#include <cuda_runtime.h>
#include <cuda_fp16.h>
#include <cuda_bf16.h>

#define N_VERTS 100000
#define N_TETS  200000
#define BATCH   64
#define ROWS    (3 * N_VERTS)      // 300000

#define DET_BLOCKS 1250            // 1250 blocks x 32 tets x 5 iters = 200000 exact
#define DET_THREADS 256

// batch permutation inside g_xTh: stored column j holds real batch sigma(j);
// sigma(t) = ((t&7)<<3)|(t>>3), self-inverse.
__device__ __forceinline__ int sigma6(int t) { return ((t & 7) << 3) | (t >> 3); }

__device__ __half g_xTh[(size_t)ROWS * BATCH];        // 38.4 MB fp16 transposed x
__device__ float  g_partial[DET_BLOCKS * BATCH];
__device__ float  g_invscale[BATCH];                  // indexed by REAL batch
__device__ unsigned g_counter;                        // zero-init, self-resetting

// ---------------------------------------------------------------------------
// Transpose x[64][300000] -> xTh[300000][64] (fp16, batch-permuted by sigma).
// ---------------------------------------------------------------------------
__global__ void __launch_bounds__(512)
k_transpose(const float* __restrict__ x)
{
    __shared__ float4 tile4[64][33];
    const float* tile_f = (const float*)tile4;        // tile_f[b*132 + r]
    const int row0 = blockIdx.x * 128;

    // ---- fill: warp w, iter j: batch b=16j+w, LDG.128 of rows 4tx..4tx+3 ----
    const int tx = threadIdx.x & 31;
    const int w  = threadIdx.x >> 5;                  // 0..15
    const int r4 = row0 + 4 * tx;
    if (r4 < ROWS) {                                  // ROWS%4==0 -> quad fully valid
        #pragma unroll
        for (int j = 0; j < 4; j++) {
            const int b = j * 16 + w;
            tile4[b][tx] = __ldcs((const float4*)(x + (size_t)b * ROWS + r4));
        }
    }
    __syncthreads();

    // ---- drain: thread (g, rr): 8 LDS (banks 4g+rr, distinct) -> STG.128 ----
    const int g   = threadIdx.x & 7;
    const int rr0 = threadIdx.x >> 3;                 // 0..63
    #pragma unroll
    for (int p = 0; p < 2; p++) {
        const int rr  = rr0 + 64 * p;
        const int row = row0 + rr;
        if (row < ROWS) {
            __half h[8];
            #pragma unroll
            for (int k = 0; k < 8; k++)
                h[k] = __float2half_rn(tile_f[(8*k + g) * 132 + rr]);
            ((uint4*)(g_xTh + (size_t)row * 64))[g] = *(const uint4*)h;
        }
    }
}

// ---------------------------------------------------------------------------
// Det kernel: warp = 4 tets; lane (q = lane>>3, o = lane&7) loads 9 LDG.128
// (8 batch-columns each) and computes 8 |det| in __half2 math (2 cols/op),
// accumulating in fp32. Last block (fenced atomic ticket) -> g_invscale.
// ---------------------------------------------------------------------------
__global__ void __launch_bounds__(DET_THREADS, 4)
k_det(const int* __restrict__ M)
{
    __shared__ __align__(16) float sSum[8][64];
    __shared__ float sQ[4][64];
    __shared__ unsigned sTicket;

    const int wid  = threadIdx.x >> 5;
    const int lane = threadIdx.x & 31;
    const int q    = lane >> 3;          // tet quarter 0..3
    const int o    = lane & 7;           // uint4 octet -> stored cols 8o..8o+7

    float acc[8];
    #pragma unroll
    for (int k = 0; k < 8; k++) acc[k] = 0.f;

    #pragma unroll 1
    for (int t0 = blockIdx.x * 32; t0 < N_TETS; t0 += DET_BLOCKS * 32) {
        const int t  = t0 + wid * 4 + q;              // exact tiling, no guard
        const int i0 = __ldg(M + 3 * t + 0);
        const int i1 = __ldg(M + 3 * t + 1);
        const int i2 = __ldg(M + 3 * t + 2);

        const uint4* pa = (const uint4*)(g_xTh + (size_t)(3 * i0) * 64) + o;
        const uint4* pb = (const uint4*)(g_xTh + (size_t)(3 * i1) * 64) + o;
        const uint4* pc = (const uint4*)(g_xTh + (size_t)(3 * i2) * 64) + o;

        // 9 independent LDG.128 (row stride = 128B = 8 uint4)
        uint4 ua0 = __ldg(pa), ua1 = __ldg(pa + 8), ua2 = __ldg(pa + 16);
        uint4 ub0 = __ldg(pb), ub1 = __ldg(pb + 8), ub2 = __ldg(pb + 16);
        uint4 uc0 = __ldg(pc), uc1 = __ldg(pc + 8), uc2 = __ldg(pc + 16);

        const __half2* A0 = (const __half2*)&ua0;
        const __half2* A1 = (const __half2*)&ua1;
        const __half2* A2 = (const __half2*)&ua2;
        const __half2* B0 = (const __half2*)&ub0;
        const __half2* B1 = (const __half2*)&ub1;
        const __half2* B2 = (const __half2*)&ub2;
        const __half2* C0 = (const __half2*)&uc0;
        const __half2* C1 = (const __half2*)&uc1;
        const __half2* C2 = (const __half2*)&uc2;

        #pragma unroll
        for (int p = 0; p < 4; p++) {
            const __half2 a0 = A0[p], a1 = A1[p], a2 = A2[p];
            const __half2 b0 = B0[p], b1 = B1[p], b2 = B2[p];
            const __half2 c0 = C0[p], c1 = C1[p], c2 = C2[p];
            const __half2 s0 = __hsub2(__hmul2(b1, c2), __hmul2(b2, c1));
            const __half2 s1 = __hsub2(__hmul2(b0, c2), __hmul2(b2, c0));
            const __half2 s2 = __hsub2(__hmul2(b0, c1), __hmul2(b1, c0));
            const __half2 d  = __habs2(__hfma2(a0, s0,
                                 __hfma2(__hneg2(a1), s1, __hmul2(a2, s2))));
            const float2 f = __half22float2(d);
            acc[2*p + 0] += f.x;
            acc[2*p + 1] += f.y;
        }
    }

    // combine the 4 tet-quarters (same columns): lanes differing in bits 3,4
    #pragma unroll
    for (int k = 0; k < 8; k++) {
        acc[k] += __shfl_xor_sync(0xffffffffu, acc[k], 8);
        acc[k] += __shfl_xor_sync(0xffffffffu, acc[k], 16);
    }
    if (lane < 8) {                      // lane o holds cols 8o..8o+7
        ((float4*)&sSum[wid][8 * lane])[0] = make_float4(acc[0], acc[1], acc[2], acc[3]);
        ((float4*)&sSum[wid][8 * lane])[1] = make_float4(acc[4], acc[5], acc[6], acc[7]);
    }
    __syncthreads();

    if (threadIdx.x < 64) {
        float s = 0.f;
        #pragma unroll
        for (int w = 0; w < 8; w++) s += sSum[w][threadIdx.x];
        g_partial[blockIdx.x * 64 + threadIdx.x] = s;
    }
    __syncthreads();

    if (threadIdx.x == 0) {
        __threadfence();
        sTicket = atomicAdd(&g_counter, 1u);
    }
    __syncthreads();

    if (sTicket == DET_BLOCKS - 1) {     // last block finishes
        __threadfence();                 // acquire partials
        {
            const int c  = threadIdx.x & 63;
            const int qq = threadIdx.x >> 6;          // 0..3
            const int K  = (DET_BLOCKS + 3) / 4;      // 313
            const int beg = qq * K;
            const int end = min(beg + K, DET_BLOCKS);
            const volatile float* p = g_partial;
            float s = 0.f;
            for (int blk = beg; blk < end; blk++)
                s += p[blk * 64 + c];
            sQ[qq][c] = s;
        }
        __syncthreads();
        if (threadIdx.x < 64) {
            float s = ((sQ[0][threadIdx.x] + sQ[1][threadIdx.x])
                     +  sQ[2][threadIdx.x]) + sQ[3][threadIdx.x];
            g_invscale[sigma6(threadIdx.x)] = 1.0f / cbrtf(s / 6.0f);  // un-permute
        }
        if (threadIdx.x == 0)
            g_counter = 0;               // reset for next graph replay
    }
}

// ---------------------------------------------------------------------------
// Output: read xTh (L2-hot), scale, inverse-transpose via conflict-free smem,
// write out[b][row] with coalesced float4 streaming stores.
// ---------------------------------------------------------------------------
__global__ void __launch_bounds__(512)
k_outT(float* __restrict__ out)
{
    __shared__ float tile_f[64 * 132];    // tile_f[real_batch*132 + r], 33 KB
    const int row0 = blockIdx.x * 128;

    const int g   = threadIdx.x & 7;
    const int rr0 = threadIdx.x >> 3;                 // 0..63
    float finv[8];
    #pragma unroll
    for (int k = 0; k < 8; k++)
        finv[k] = g_invscale[8*k + g];                // real batch of half k

    #pragma unroll
    for (int p = 0; p < 2; p++) {
        const int rr  = rr0 + 64 * p;
        const int row = row0 + rr;
        if (row < ROWS) {
            uint4 u = *((const uint4*)(g_xTh + (size_t)row * 64) + g);
            const __half2* h2 = (const __half2*)&u;
            #pragma unroll
            for (int k2 = 0; k2 < 4; k2++) {
                float2 f = __half22float2(h2[k2]);
                tile_f[(8*(2*k2+0) + g) * 132 + rr] = f.x * finv[2*k2+0];
                tile_f[(8*(2*k2+1) + g) * 132 + rr] = f.y * finv[2*k2+1];
            }
        }
    }
    __syncthreads();

    #pragma unroll
    for (int j = 0; j < 4; j++) {
        const int item = j * 512 + threadIdx.x;       // 0..2047
        const int b    = item >> 5;                   // real batch 0..63
        const int quad = item & 31;                   // row quad within tile
        const int row  = row0 + 4 * quad;
        if (row < ROWS) {
            float4 v = *(const float4*)(tile_f + b * 132 + 4 * quad);
            __stcs((float4*)(out + (size_t)b * ROWS + row), v);
        }
    }
}

// ---------------------------------------------------------------------------
extern "C" void kernel_launch(void* const* d_in, const int* in_sizes, int n_in,
                              void* d_out, int out_size)
{
    // x: 19,200,000 float32 ; M: 600,000 int32 — select by element count.
    const float* x;
    const int*   M;
    if (in_sizes[0] == 19200000) { x = (const float*)d_in[0]; M = (const int*)d_in[1]; }
    else                         { x = (const float*)d_in[1]; M = (const int*)d_in[0]; }
    float* o = (float*)d_out;

    const int tBlocks = (ROWS + 127) / 128;    // 2344
    k_transpose<<<tBlocks, 512>>>(x);
    k_det<<<DET_BLOCKS, DET_THREADS>>>(M);
    k_outT<<<tBlocks, 512>>>(o);
}

// round 16
// speedup vs baseline: 1.0427x; 1.0427x over previous
#include <cuda_runtime.h>
#include <cuda_fp16.h>
#include <cuda_bf16.h>

#define N_VERTS 100000
#define N_TETS  200000
#define BATCH   64
#define ROWS    (3 * N_VERTS)      // 300000

#define DET_BLOCKS 592             // 4 CTAs/SM x 512 thr = full occupancy
#define DET_THREADS 512            // 16 warps; 32 tets per block-iteration
#define DET_STEP   (DET_BLOCKS * 32)   // 18944 (same stride as R12)

// batch permutation inside g_xTh: stored column j holds real batch sigma(j);
// sigma(t) = ((t&7)<<3)|(t>>3), self-inverse.
__device__ __forceinline__ int sigma6(int t) { return ((t & 7) << 3) | (t >> 3); }

__device__ __half g_xTh[(size_t)ROWS * BATCH];        // 38.4 MB fp16 transposed x
__device__ float  g_partial[DET_BLOCKS * BATCH];
__device__ float  g_invscale[BATCH];                  // indexed by REAL batch
__device__ unsigned g_counter;                        // zero-init, self-resetting

// ---------------------------------------------------------------------------
// Transpose x[64][300000] -> xTh[300000][64] (fp16, batch-permuted by sigma).
// ---------------------------------------------------------------------------
__global__ void __launch_bounds__(512)
k_transpose(const float* __restrict__ x)
{
    __shared__ float4 tile4[64][33];
    const float* tile_f = (const float*)tile4;        // tile_f[b*132 + r]
    const int row0 = blockIdx.x * 128;

    // ---- fill: warp w, iter j: batch b=16j+w, LDG.128 of rows 4tx..4tx+3 ----
    const int tx = threadIdx.x & 31;
    const int w  = threadIdx.x >> 5;                  // 0..15
    const int r4 = row0 + 4 * tx;
    if (r4 < ROWS) {                                  // ROWS%4==0 -> quad fully valid
        #pragma unroll
        for (int j = 0; j < 4; j++) {
            const int b = j * 16 + w;
            tile4[b][tx] = __ldcs((const float4*)(x + (size_t)b * ROWS + r4));
        }
    }
    __syncthreads();

    // ---- drain: thread (g, rr): 8 LDS (banks 4g+rr, distinct) -> STG.128 ----
    const int g   = threadIdx.x & 7;
    const int rr0 = threadIdx.x >> 3;                 // 0..63
    #pragma unroll
    for (int p = 0; p < 2; p++) {
        const int rr  = rr0 + 64 * p;
        const int row = row0 + rr;
        if (row < ROWS) {
            __half h[8];
            #pragma unroll
            for (int k = 0; k < 8; k++)
                h[k] = __float2half_rn(tile_f[(8*k + g) * 132 + rr]);
            ((uint4*)(g_xTh + (size_t)row * 64))[g] = *(const uint4*)h;
        }
    }
}

// ---------------------------------------------------------------------------
// uint2 (4 fp16) -> float4
// ---------------------------------------------------------------------------
__device__ __forceinline__ float4 h4f(uint2 u)
{
    float2 f0 = __half22float2(*(const __half2*)&u.x);
    float2 f1 = __half22float2(*(const __half2*)&u.y);
    return make_float4(f0.x, f0.y, f1.x, f1.y);
}

// ---------------------------------------------------------------------------
// Det kernel (R12-proven inner loop): each warp handles 2 tets x 64 columns
// per iteration; lane = (tetHalf = lane>>4, colGroup bg = lane&15); 9
// coalesced LDG.64 per lane; fp32 accumulation. 512 threads / 592 blocks for
// full occupancy and a halved epilogue.
// ---------------------------------------------------------------------------
__global__ void __launch_bounds__(DET_THREADS)
k_det(const int* __restrict__ M)
{
    __shared__ float sSum[16][64];
    __shared__ float sQ[4][64];
    __shared__ unsigned sTicket;

    const int wid  = threadIdx.x >> 5;   // 0..15
    const int lane = threadIdx.x & 31;
    const int half = lane >> 4;
    const int bg   = lane & 15;

    float acc0 = 0.f, acc1 = 0.f, acc2 = 0.f, acc3 = 0.f;

    #pragma unroll 2
    for (int base = blockIdx.x * 32; base < N_TETS; base += DET_STEP) {
        const int t  = base + wid * 2 + half;
        const int i0 = __ldg(M + 3 * t + 0);
        const int i1 = __ldg(M + 3 * t + 1);
        const int i2 = __ldg(M + 3 * t + 2);

        const uint2* pa = (const uint2*)(g_xTh + (size_t)(3 * i0) * 64) + bg;
        const uint2* pb = (const uint2*)(g_xTh + (size_t)(3 * i1) * 64) + bg;
        const uint2* pc = (const uint2*)(g_xTh + (size_t)(3 * i2) * 64) + bg;

        // 9 independent LDG.64 — raw loads first so they batch
        uint2 ua0 = __ldg(pa), ua1 = __ldg(pa + 16), ua2 = __ldg(pa + 32);
        uint2 ub0 = __ldg(pb), ub1 = __ldg(pb + 16), ub2 = __ldg(pb + 32);
        uint2 uc0 = __ldg(pc), uc1 = __ldg(pc + 16), uc2 = __ldg(pc + 32);

        float4 ax = h4f(ua0), ay = h4f(ua1), az = h4f(ua2);
        float4 bx = h4f(ub0), by = h4f(ub1), bz = h4f(ub2);
        float4 cx = h4f(uc0), cy = h4f(uc1), cz = h4f(uc2);

        acc0 += fabsf(ax.x * (by.x * cz.x - bz.x * cy.x)
                    - ay.x * (bx.x * cz.x - bz.x * cx.x)
                    + az.x * (bx.x * cy.x - by.x * cx.x));
        acc1 += fabsf(ax.y * (by.y * cz.y - bz.y * cy.y)
                    - ay.y * (bx.y * cz.y - bz.y * cx.y)
                    + az.y * (bx.y * cy.y - by.y * cx.y));
        acc2 += fabsf(ax.z * (by.z * cz.z - bz.z * cy.z)
                    - ay.z * (bx.z * cz.z - bz.z * cx.z)
                    + az.z * (bx.z * cy.z - by.z * cx.z));
        acc3 += fabsf(ax.w * (by.w * cz.w - bz.w * cy.w)
                    - ay.w * (bx.w * cz.w - bz.w * cx.w)
                    + az.w * (bx.w * cy.w - by.w * cx.w));
    }

    acc0 += __shfl_down_sync(0xffffffffu, acc0, 16);
    acc1 += __shfl_down_sync(0xffffffffu, acc1, 16);
    acc2 += __shfl_down_sync(0xffffffffu, acc2, 16);
    acc3 += __shfl_down_sync(0xffffffffu, acc3, 16);
    if (lane < 16)
        ((float4*)sSum[wid])[bg] = make_float4(acc0, acc1, acc2, acc3);
    __syncthreads();

    if (threadIdx.x < 64) {
        float s = 0.f;
        #pragma unroll
        for (int w = 0; w < 16; w++) s += sSum[w][threadIdx.x];
        g_partial[blockIdx.x * 64 + threadIdx.x] = s;
    }
    __syncthreads();

    if (threadIdx.x == 0) {
        __threadfence();
        sTicket = atomicAdd(&g_counter, 1u);
    }
    __syncthreads();

    if (sTicket == DET_BLOCKS - 1) {     // last block finishes
        __threadfence();                 // acquire partials
        if (threadIdx.x < 256) {
            const int c = threadIdx.x & 63;
            const int q = threadIdx.x >> 6;           // 0..3
            const volatile float* p = g_partial;
            float s = 0.f;
            const int beg = q * (DET_BLOCKS / 4), end = beg + DET_BLOCKS / 4;
            for (int blk = beg; blk < end; blk++)
                s += p[blk * 64 + c];
            sQ[q][c] = s;
        }
        __syncthreads();
        if (threadIdx.x < 64) {
            float s = ((sQ[0][threadIdx.x] + sQ[1][threadIdx.x])
                     +  sQ[2][threadIdx.x]) + sQ[3][threadIdx.x];
            g_invscale[sigma6(threadIdx.x)] = 1.0f / cbrtf(s / 6.0f);  // un-permute
        }
        if (threadIdx.x == 0)
            g_counter = 0;               // reset for next graph replay
    }
}

// ---------------------------------------------------------------------------
// Output: read xTh (L2-hot), scale, inverse-transpose via conflict-free smem,
// write out[b][row] with coalesced float4 streaming stores.
// ---------------------------------------------------------------------------
__global__ void __launch_bounds__(512)
k_outT(float* __restrict__ out)
{
    __shared__ float tile_f[64 * 132];    // tile_f[real_batch*132 + r], 33 KB
    const int row0 = blockIdx.x * 128;

    const int g   = threadIdx.x & 7;
    const int rr0 = threadIdx.x >> 3;                 // 0..63
    float finv[8];
    #pragma unroll
    for (int k = 0; k < 8; k++)
        finv[k] = g_invscale[8*k + g];                // real batch of half k

    #pragma unroll
    for (int p = 0; p < 2; p++) {
        const int rr  = rr0 + 64 * p;
        const int row = row0 + rr;
        if (row < ROWS) {
            uint4 u = *((const uint4*)(g_xTh + (size_t)row * 64) + g);
            const __half2* h2 = (const __half2*)&u;
            #pragma unroll
            for (int k2 = 0; k2 < 4; k2++) {
                float2 f = __half22float2(h2[k2]);
                tile_f[(8*(2*k2+0) + g) * 132 + rr] = f.x * finv[2*k2+0];
                tile_f[(8*(2*k2+1) + g) * 132 + rr] = f.y * finv[2*k2+1];
            }
        }
    }
    __syncthreads();

    #pragma unroll
    for (int j = 0; j < 4; j++) {
        const int item = j * 512 + threadIdx.x;       // 0..2047
        const int b    = item >> 5;                   // real batch 0..63
        const int quad = item & 31;                   // row quad within tile
        const int row  = row0 + 4 * quad;
        if (row < ROWS) {
            float4 v = *(const float4*)(tile_f + b * 132 + 4 * quad);
            __stcs((float4*)(out + (size_t)b * ROWS + row), v);
        }
    }
}

// ---------------------------------------------------------------------------
extern "C" void kernel_launch(void* const* d_in, const int* in_sizes, int n_in,
                              void* d_out, int out_size)
{
    // x: 19,200,000 float32 ; M: 600,000 int32 — select by element count.
    const float* x;
    const int*   M;
    if (in_sizes[0] == 19200000) { x = (const float*)d_in[0]; M = (const int*)d_in[1]; }
    else                         { x = (const float*)d_in[1]; M = (const int*)d_in[0]; }
    float* o = (float*)d_out;

    const int tBlocks = (ROWS + 127) / 128;    // 2344
    k_transpose<<<tBlocks, 512>>>(x);
    k_det<<<DET_BLOCKS, DET_THREADS>>>(M);
    k_outT<<<tBlocks, 512>>>(o);
}